// round 15
// baseline (speedup 1.0000x reference)
#include <cuda_runtime.h>
#include <cstdint>

// MiniBatchDiscrimination: out = concat(x, o_b)
//   m = x @ T -> [B, F, K]  (g_m2[f][b][k])
//   norm[i,j,f] = sum_k |m[i,f,k]-m[j,f,k]|;  o_b[j,f] = sum_i exp(-norm) - 1
// Per-term fp32 absorption: (1+ex)-1 == +0.0 exactly when ex <= 2^-24
// (norm >= 16.64). Bounds (scalar row-sum and 4-group L1) are <= norm, so
// pairs filtered at bound >= 18 are guaranteed-absorbed.
// R14 lesson: ANY dense scan of all 8.4M pairs floors at ~8us. This round
// prunes candidates structurally: counting-sort rows by row-sum S into
// width-20 bins; pairs with |dS| < 18 are provably in same/adjacent bins ->
// each row scans only ~28 candidates (18x fewer evals). Dedup by perm
// position. Survivor chain: scalar check -> 4-group bound -> exact fp32
// norm+exp+absorb; absorbed +0.0 adds are skipped (bitwise identical).
// GEMM: tf32 mma.sync 1-pass, 4 in-CTA K-split quarters now decoupled by
// PER-QUARTER NAMED BARRIERS (bar.sync qid+1,128) so quarters' LDS/MMA
// phases interleave; epilogue reduction distributed across quarters.
// NOTE (R5): no __threadfence fusion — CCTL.IVALL cost ~28us.
#define B_SZ   512
#define IN_F   512
#define OUT_F  64
#define K_DIMS 16
#define NCOL   1024
#define OUT_W  576

#define THRESH  18.0f
#define NB_BINS 42          // width-20 bins covering S in [-420, 420]

// per-quarter smem (words): Ah|Bh, double buffered
#define AW    36
#define BW    72
#define ASZ   (64 * AW)                       // 2304
#define BSZ   (32 * BW)                       // 2304
#define BUF1  (ASZ + BSZ)                     // 4608 words = 18432 B
#define QWORDS (2 * BUF1)                     // 9216 words per quarter
#define GEMM_SMEM_BYTES (4 * QWORDS * 4)      // 147456 B

__device__ float g_m2[OUT_F * B_SZ * K_DIMS];   // [f][b][k]  2 MB
__device__ float g_g4[OUT_F * B_SZ * 4];        // 4-group sums, 0.5 MB

// ---------------- tf32 helpers (sm_80-level PTX, valid on sm_100) ----------
__device__ __forceinline__ uint32_t f2tf32(float x) {
    uint32_t r;
    asm("cvt.rna.tf32.f32 %0, %1;" : "=r"(r) : "f"(x));
    return r;
}
__device__ __forceinline__ void mma8(float (&c)[4], const uint32_t (&a)[4],
                                     const uint32_t (&b)[2]) {
    asm volatile("mma.sync.aligned.m16n8k8.row.col.f32.tf32.tf32.f32 "
                 "{%0,%1,%2,%3}, {%4,%5,%6,%7}, {%8,%9}, {%0,%1,%2,%3};"
                 : "+f"(c[0]), "+f"(c[1]), "+f"(c[2]), "+f"(c[3])
                 : "r"(a[0]), "r"(a[1]), "r"(a[2]), "r"(a[3]),
                   "r"(b[0]), "r"(b[1]));
}
#define BARQ(id) asm volatile("bar.sync %0, 128;" :: "r"(id) : "memory")

// ---------------------------------------------------------------------------
// Kernel 1: C[512,1024] = X @ T, tf32 1-pass. 512 threads = 4 quarters of
// 128 (qid = t>>7); quarter q covers K [q*128, q*128+128) in 4 chunks of 32,
// double-buffered, synced by its OWN named barrier (qid+1) so quarters
// drift and interleave pipe phases. All quarters dump accs; each reduces
// and writes the epilogue for 2 of the 8 fragments.
// ---------------------------------------------------------------------------
__global__ void __launch_bounds__(512) gemm_tc(const float* __restrict__ X,
                                               const float* __restrict__ T,
                                               float* __restrict__ out) {
    extern __shared__ uint32_t sm[];

    const int t = threadIdx.x;
    const int qid = t >> 7, ts = t & 127;
    const int w = ts >> 5, l = ts & 31;
    const int n0 = blockIdx.x * 64, m0 = blockIdx.y * 64;
    const int kb = qid * 128;
    const int wm0 = (w & 1) * 32, wn0 = (w >> 1) * 32;
    const int g = l >> 2, tg = l & 3;
    const int barid = qid + 1;                 // 0 reserved for __syncthreads
    uint32_t* qbase = sm + qid * QWORDS;

    // zero out's o_b region (32768 floats over first 64 CTAs)
    {
        int cta = blockIdx.y * 16 + blockIdx.x;   // 0..127
        if (cta < 64) {
            int idx = cta * 512 + t;
            out[(idx >> 6) * OUT_W + IN_F + (idx & 63)] = 0.f;
        }
    }

    float acc[2][4][4];
#pragma unroll
    for (int mf = 0; mf < 2; ++mf)
#pragma unroll
        for (int nf = 0; nf < 4; ++nf)
#pragma unroll
            for (int q = 0; q < 4; ++q) acc[mf][nf][q] = 0.f;

    float4 ap[4], bp[4];
#define LOADAB(kk)                                                            \
    _Pragma("unroll") for (int i = 0; i < 4; ++i) {                           \
        int idx4 = ts + i * 128;                                              \
        int ra = idx4 >> 3, ca = idx4 & 7;                                    \
        ap[i] = *(const float4*)&X[(m0 + ra) * IN_F + (kk) + ca * 4];         \
        int rb = idx4 >> 4, cb = idx4 & 15;                                   \
        bp[i] = *(const float4*)&T[((kk) + rb) * NCOL + n0 + cb * 4];         \
    }

#define CVTSTORE(base)                                                        \
    _Pragma("unroll") for (int i = 0; i < 4; ++i) {                           \
        uint32_t* Ah_ = (base); uint32_t* Bh_ = (base) + ASZ;                 \
        int idx4 = ts + i * 128;                                              \
        int ra = idx4 >> 3, ca = idx4 & 7;                                    \
        float4 v = ap[i];                                                     \
        *(uint4*)&Ah_[ra * AW + ca * 4] = make_uint4(                         \
            f2tf32(v.x), f2tf32(v.y), f2tf32(v.z), f2tf32(v.w));              \
        int rb = idx4 >> 4, cb = idx4 & 15;                                   \
        float4 u = bp[i];                                                     \
        *(uint4*)&Bh_[rb * BW + cb * 4] = make_uint4(                         \
            f2tf32(u.x), f2tf32(u.y), f2tf32(u.z), f2tf32(u.w));              \
    }

    LOADAB(kb);
    CVTSTORE(qbase);
    BARQ(barid);

    for (int c = 0; c < 4; ++c) {
        const bool more = (c < 3);
        uint32_t* cb_ = qbase + (c & 1) * BUF1;
        uint32_t* nb_ = qbase + ((c + 1) & 1) * BUF1;

        if (more) LOADAB(kb + (c + 1) * 32);   // LDG hidden under MMA

        uint32_t* Ah_ = cb_;
        uint32_t* Bh_ = cb_ + ASZ;

#pragma unroll
        for (int s = 0; s < 4; ++s) {
            const int k8 = s * 8;
            uint32_t ah[2][4], bh[4][2];
#pragma unroll
            for (int mf = 0; mf < 2; ++mf) {
                int r0 = wm0 + mf * 16 + g;
                ah[mf][0] = Ah_[r0 * AW + k8 + tg];
                ah[mf][1] = Ah_[(r0 + 8) * AW + k8 + tg];
                ah[mf][2] = Ah_[r0 * AW + k8 + tg + 4];
                ah[mf][3] = Ah_[(r0 + 8) * AW + k8 + tg + 4];
            }
#pragma unroll
            for (int nf = 0; nf < 4; ++nf) {
                int c0 = wn0 + nf * 8 + g;
                bh[nf][0] = Bh_[(k8 + tg) * BW + c0];
                bh[nf][1] = Bh_[(k8 + tg + 4) * BW + c0];
            }
#pragma unroll
            for (int mf = 0; mf < 2; ++mf)
#pragma unroll
                for (int nf = 0; nf < 4; ++nf) mma8(acc[mf][nf], ah[mf], bh[nf]);
        }

        if (more) CVTSTORE(nb_);               // write other buffer
        BARQ(barid);
    }

    // ---- all quarters dump accs to their own (now idle) smem region ----
    {
        float* red = (float*)qbase;
        int r = 0;
#pragma unroll
        for (int mf = 0; mf < 2; ++mf)
#pragma unroll
            for (int nf = 0; nf < 4; ++nf)
#pragma unroll
                for (int q = 0; q < 4; ++q)
                    red[(r++) * 128 + ts] = acc[mf][nf][q];
    }
    __syncthreads();

    // ---- each quarter reduces + writes epilogue for frags {2qid, 2qid+1}
#pragma unroll
    for (int e = 0; e < 2; ++e) {
        const int fi = 2 * qid + e;
        const int mf = fi >> 2, nf = fi & 3;
        float c0 = 0.f, c1 = 0.f, c2 = 0.f, c3 = 0.f;
#pragma unroll
        for (int qq = 0; qq < 4; ++qq) {
            const float* red = (const float*)(sm + qq * QWORDS);
            c0 += red[(fi * 4 + 0) * 128 + ts];
            c1 += red[(fi * 4 + 1) * 128 + ts];
            c2 += red[(fi * 4 + 2) * 128 + ts];
            c3 += red[(fi * 4 + 3) * 128 + ts];
        }
        int row = m0 + wm0 + mf * 16 + g;
        int col = n0 + wn0 + nf * 8 + 2 * tg;
        int f = col >> 4, k = col & 15;
        *(float2*)&g_m2[f * (B_SZ * K_DIMS) + row * K_DIMS + k] =
            make_float2(c0, c1);
        *(float2*)&g_m2[f * (B_SZ * K_DIMS) + (row + 8) * K_DIMS + k] =
            make_float2(c2, c3);
        float s0 = c0 + c1, s1 = c2 + c3;
        s0 += __shfl_xor_sync(0xffffffffu, s0, 1);
        s1 += __shfl_xor_sync(0xffffffffu, s1, 1);
        if ((tg & 1) == 0) {
            int grp = ((nf & 1) << 1) | (tg >> 1);
            g_g4[f * (B_SZ * 4) + row * 4 + grp] = s0;
            g_g4[f * (B_SZ * 4) + (row + 8) * 4 + grp] = s1;
        }
    }
}

// ---------------------------------------------------------------------------
// Kernel 2: bucket-pruned filter. Block (f, h): 256 threads; each thread
// owns row j = 2*tid + h. Counting-sort rows by S into width-20 bins; scan
// only [prev-bin start, own perm pos): ~28 candidates/row. Chain: scalar
// check -> 4-group bound -> exact fp32 norm+exp+absorb; skip +0.0 adds.
// x-copy folded in.
// ---------------------------------------------------------------------------
__global__ void __launch_bounds__(256) boundexp(const float* __restrict__ X,
                                                float* __restrict__ out) {
    __shared__ float sv[B_SZ];                 // row sums
    __shared__ float sg4[B_SZ * 4];            // 4-group sums
    __shared__ int   binOf[B_SZ], posOf[B_SZ];
    __shared__ unsigned short perm[B_SZ];
    __shared__ int cnt[NB_BINS], bstart[NB_BINS + 1], ofs[NB_BINS];

    const int f = blockIdx.x, h = blockIdx.y;  // h in {0,1}
    const int tid = threadIdx.x;

    // folded x-copy: 65536 float4s over 128 blocks (512 each)
    {
        int base4 = (f * 2 + h) * 512;
#pragma unroll
        for (int k = 0; k < 2; ++k) {
            int idx4 = base4 + tid + k * 256;
            int b = idx4 >> 7, c4 = idx4 & 127;
            ((float4*)(out + b * OUT_W))[c4] =
                ((const float4*)(X + b * IN_F))[c4];
        }
    }

    if (tid < NB_BINS) cnt[tid] = 0;
    __syncthreads();

    // stage group sums + row sums, histogram bins
    {
        const float4* src = (const float4*)(g_g4 + f * (B_SZ * 4));
        for (int r = tid; r < B_SZ; r += 256) {
            float4 v = src[r];
            ((float4*)sg4)[r] = v;
            float s = (v.x + v.y) + (v.z + v.w);
            sv[r] = s;
            int b = (int)((s + 420.f) * 0.05f);
            b = max(0, min(NB_BINS - 1, b));
            binOf[r] = b;
            atomicAdd(&cnt[b], 1);
        }
    }
    __syncthreads();
    if (tid == 0) {
        int a = 0;
        for (int b = 0; b < NB_BINS; ++b) { bstart[b] = a; a += cnt[b]; }
        bstart[NB_BINS] = a;
    }
    __syncthreads();
    if (tid < NB_BINS) ofs[tid] = bstart[tid];
    __syncthreads();
    for (int r = tid; r < B_SZ; r += 256) {
        int pos = atomicAdd(&ofs[binOf[r]], 1);
        perm[pos] = (unsigned short)r;
        posOf[r] = pos;
    }
    __syncthreads();

    // scan: row j's candidates are perm[qstart .. myPos)
    const int j = 2 * tid + h;
    const int myBin = binOf[j];
    const int myPos = posOf[j];
    const int qstart = (myBin > 0) ? bstart[myBin - 1] : 0;
    const float sj = sv[j];
    const float4 hj = ((const float4*)sg4)[j];
    const float4* mf4 = (const float4*)(g_m2 + f * (B_SZ * K_DIMS));

    for (int q = qstart; q < myPos; ++q) {
        int i = perm[q];
        if (fabsf(sj - sv[i]) >= THRESH) continue;      // scalar bound
        float4 a = ((const float4*)sg4)[i];
        float bnd = (fabsf(a.x - hj.x) + fabsf(a.y - hj.y)) +
                    (fabsf(a.z - hj.z) + fabsf(a.w - hj.w));
        if (bnd >= THRESH) continue;                    // 4-group bound
        const float4* mi = mf4 + i * 4;                 // exact (L2)
        const float4* mj = mf4 + j * 4;
        float norm = 0.f;
#pragma unroll
        for (int pp = 0; pp < 4; ++pp) {
            float4 u = mi[pp], v = mj[pp];
            norm += (fabsf(u.x - v.x) + fabsf(u.y - v.y)) +
                    (fabsf(u.z - v.z) + fabsf(u.w - v.w));
        }
        // fp32 absorption vs self-term 1.0: ex <= 2^-24 -> exactly +0.0f;
        // skipping a +0.0 add is bitwise identical.
        float ex = __expf(-norm);
        float exa = __fadd_rn(__fadd_rn(1.0f, ex), -1.0f);
        if (exa != 0.0f) {
            atomicAdd(&out[j * OUT_W + IN_F + f], exa); // both sides
            atomicAdd(&out[i * OUT_W + IN_F + f], exa);
        }
    }
}

// ---------------------------------------------------------------------------
extern "C" void kernel_launch(void* const* d_in, const int* in_sizes, int n_in,
                              void* d_out, int out_size) {
    const float* X = (const float*)d_in[0];   // [512, 512]
    const float* T = (const float*)d_in[1];   // [512, 64, 16]
    float* out = (float*)d_out;               // [512, 576]

    // host-side attribute set (not a stream op; capture-safe, deterministic)
    cudaFuncSetAttribute(gemm_tc, cudaFuncAttributeMaxDynamicSharedMemorySize,
                         GEMM_SMEM_BYTES);

    gemm_tc<<<dim3(16, 8), 512, GEMM_SMEM_BYTES>>>(X, T, out);
    boundexp<<<dim3(OUT_F, 2), 256>>>(X, out);
}

// round 16
// speedup vs baseline: 1.2783x; 1.2783x over previous
#include <cuda_runtime.h>
#include <cstdint>

// MiniBatchDiscrimination: out = concat(x, o_b)
//   m = x @ T -> [B, F, K]  (g_m2[f][b][k])
//   norm[i,j,f] = sum_k |m[i,f,k]-m[j,f,k]|;  o_b[j,f] = sum_i exp(-norm) - 1
// Per-term fp32 absorption: (1+ex)-1 == +0.0 exactly when ex <= 2^-24
// (norm >= 16.64); bounds <= norm, so pairs filtered at >= 18 are
// guaranteed-absorbed and +0.0 adds may be skipped (bitwise identical).
// R15 lessons: bucket pruning killed parallelism (occ 10%) -> reverted to
// R14's wide scan; but the named-barrier gemm decoupling helped (~2.5us) ->
// kept. New: phase-1 filter uses the SCALAR row-sum bound |S_i - S_j|
// (LDS.32 + FADD + FSETP + pred-OR ~ 5 slots/eval vs 11); only ~11% reach
// the 4-group bound, ~1.7% the exact fp32 norm+exp.
// GEMM: tf32 mma.sync 1-pass, 4 in-CTA K-split quarters decoupled by
// per-quarter named barriers; distributed epilogue reduction.
// NOTE (R5): no __threadfence fusion — CCTL.IVALL cost ~28us.
#define B_SZ   512
#define IN_F   512
#define OUT_F  64
#define K_DIMS 16
#define NCOL   1024
#define OUT_W  576

#define THRESH 18.0f

// per-quarter smem (words): Ah|Bh, double buffered
#define AW    36
#define BW    72
#define ASZ   (64 * AW)                       // 2304
#define BSZ   (32 * BW)                       // 2304
#define BUF1  (ASZ + BSZ)                     // 4608 words = 18432 B
#define QWORDS (2 * BUF1)                     // 9216 words per quarter
#define GEMM_SMEM_BYTES (4 * QWORDS * 4)      // 147456 B

__device__ float g_m2[OUT_F * B_SZ * K_DIMS];   // [f][b][k]  2 MB
__device__ float g_g4[OUT_F * B_SZ * 4];        // 4-group sums, 0.5 MB

// ---------------- tf32 helpers (sm_80-level PTX, valid on sm_100) ----------
__device__ __forceinline__ uint32_t f2tf32(float x) {
    uint32_t r;
    asm("cvt.rna.tf32.f32 %0, %1;" : "=r"(r) : "f"(x));
    return r;
}
__device__ __forceinline__ void mma8(float (&c)[4], const uint32_t (&a)[4],
                                     const uint32_t (&b)[2]) {
    asm volatile("mma.sync.aligned.m16n8k8.row.col.f32.tf32.tf32.f32 "
                 "{%0,%1,%2,%3}, {%4,%5,%6,%7}, {%8,%9}, {%0,%1,%2,%3};"
                 : "+f"(c[0]), "+f"(c[1]), "+f"(c[2]), "+f"(c[3])
                 : "r"(a[0]), "r"(a[1]), "r"(a[2]), "r"(a[3]),
                   "r"(b[0]), "r"(b[1]));
}
#define BARQ(id) asm volatile("bar.sync %0, 128;" :: "r"(id) : "memory")

// ---------------------------------------------------------------------------
// Kernel 1: C[512,1024] = X @ T, tf32 1-pass. 512 threads = 4 quarters of
// 128 (qid = t>>7); quarter q covers K [q*128, q*128+128) in 4 chunks of 32,
// double-buffered, synced by its OWN named barrier (qid+1). All quarters
// dump accs; each reduces + writes the epilogue for 2 of the 8 fragments.
// ---------------------------------------------------------------------------
__global__ void __launch_bounds__(512) gemm_tc(const float* __restrict__ X,
                                               const float* __restrict__ T,
                                               float* __restrict__ out) {
    extern __shared__ uint32_t sm[];

    const int t = threadIdx.x;
    const int qid = t >> 7, ts = t & 127;
    const int w = ts >> 5, l = ts & 31;
    const int n0 = blockIdx.x * 64, m0 = blockIdx.y * 64;
    const int kb = qid * 128;
    const int wm0 = (w & 1) * 32, wn0 = (w >> 1) * 32;
    const int g = l >> 2, tg = l & 3;
    const int barid = qid + 1;                 // 0 reserved for __syncthreads
    uint32_t* qbase = sm + qid * QWORDS;

    // zero out's o_b region (32768 floats over first 64 CTAs)
    {
        int cta = blockIdx.y * 16 + blockIdx.x;   // 0..127
        if (cta < 64) {
            int idx = cta * 512 + t;
            out[(idx >> 6) * OUT_W + IN_F + (idx & 63)] = 0.f;
        }
    }

    float acc[2][4][4];
#pragma unroll
    for (int mf = 0; mf < 2; ++mf)
#pragma unroll
        for (int nf = 0; nf < 4; ++nf)
#pragma unroll
            for (int q = 0; q < 4; ++q) acc[mf][nf][q] = 0.f;

    float4 ap[4], bp[4];
#define LOADAB(kk)                                                            \
    _Pragma("unroll") for (int i = 0; i < 4; ++i) {                           \
        int idx4 = ts + i * 128;                                              \
        int ra = idx4 >> 3, ca = idx4 & 7;                                    \
        ap[i] = *(const float4*)&X[(m0 + ra) * IN_F + (kk) + ca * 4];         \
        int rb = idx4 >> 4, cb = idx4 & 15;                                   \
        bp[i] = *(const float4*)&T[((kk) + rb) * NCOL + n0 + cb * 4];         \
    }

#define CVTSTORE(base)                                                        \
    _Pragma("unroll") for (int i = 0; i < 4; ++i) {                           \
        uint32_t* Ah_ = (base); uint32_t* Bh_ = (base) + ASZ;                 \
        int idx4 = ts + i * 128;                                              \
        int ra = idx4 >> 3, ca = idx4 & 7;                                    \
        float4 v = ap[i];                                                     \
        *(uint4*)&Ah_[ra * AW + ca * 4] = make_uint4(                         \
            f2tf32(v.x), f2tf32(v.y), f2tf32(v.z), f2tf32(v.w));              \
        int rb = idx4 >> 4, cb = idx4 & 15;                                   \
        float4 u = bp[i];                                                     \
        *(uint4*)&Bh_[rb * BW + cb * 4] = make_uint4(                         \
            f2tf32(u.x), f2tf32(u.y), f2tf32(u.z), f2tf32(u.w));              \
    }

    LOADAB(kb);
    CVTSTORE(qbase);
    BARQ(barid);

    for (int c = 0; c < 4; ++c) {
        const bool more = (c < 3);
        uint32_t* cb_ = qbase + (c & 1) * BUF1;
        uint32_t* nb_ = qbase + ((c + 1) & 1) * BUF1;

        if (more) LOADAB(kb + (c + 1) * 32);   // LDG hidden under MMA

        uint32_t* Ah_ = cb_;
        uint32_t* Bh_ = cb_ + ASZ;

#pragma unroll
        for (int s = 0; s < 4; ++s) {
            const int k8 = s * 8;
            uint32_t ah[2][4], bh[4][2];
#pragma unroll
            for (int mf = 0; mf < 2; ++mf) {
                int r0 = wm0 + mf * 16 + g;
                ah[mf][0] = Ah_[r0 * AW + k8 + tg];
                ah[mf][1] = Ah_[(r0 + 8) * AW + k8 + tg];
                ah[mf][2] = Ah_[r0 * AW + k8 + tg + 4];
                ah[mf][3] = Ah_[(r0 + 8) * AW + k8 + tg + 4];
            }
#pragma unroll
            for (int nf = 0; nf < 4; ++nf) {
                int c0 = wn0 + nf * 8 + g;
                bh[nf][0] = Bh_[(k8 + tg) * BW + c0];
                bh[nf][1] = Bh_[(k8 + tg + 4) * BW + c0];
            }
#pragma unroll
            for (int mf = 0; mf < 2; ++mf)
#pragma unroll
                for (int nf = 0; nf < 4; ++nf) mma8(acc[mf][nf], ah[mf], bh[nf]);
        }

        if (more) CVTSTORE(nb_);               // write other buffer
        BARQ(barid);
    }

    // ---- all quarters dump accs to their own (now idle) smem region ----
    {
        float* red = (float*)qbase;
        int r = 0;
#pragma unroll
        for (int mf = 0; mf < 2; ++mf)
#pragma unroll
            for (int nf = 0; nf < 4; ++nf)
#pragma unroll
                for (int q = 0; q < 4; ++q)
                    red[(r++) * 128 + ts] = acc[mf][nf][q];
    }
    __syncthreads();

    // ---- each quarter reduces + writes epilogue for frags {2qid, 2qid+1}
#pragma unroll
    for (int e = 0; e < 2; ++e) {
        const int fi = 2 * qid + e;
        const int mf = fi >> 2, nf = fi & 3;
        float c0 = 0.f, c1 = 0.f, c2 = 0.f, c3 = 0.f;
#pragma unroll
        for (int qq = 0; qq < 4; ++qq) {
            const float* red = (const float*)(sm + qq * QWORDS);
            c0 += red[(fi * 4 + 0) * 128 + ts];
            c1 += red[(fi * 4 + 1) * 128 + ts];
            c2 += red[(fi * 4 + 2) * 128 + ts];
            c3 += red[(fi * 4 + 3) * 128 + ts];
        }
        int row = m0 + wm0 + mf * 16 + g;
        int col = n0 + wn0 + nf * 8 + 2 * tg;
        int f = col >> 4, k = col & 15;
        *(float2*)&g_m2[f * (B_SZ * K_DIMS) + row * K_DIMS + k] =
            make_float2(c0, c1);
        *(float2*)&g_m2[f * (B_SZ * K_DIMS) + (row + 8) * K_DIMS + k] =
            make_float2(c2, c3);
        float s0 = c0 + c1, s1 = c2 + c3;
        s0 += __shfl_xor_sync(0xffffffffu, s0, 1);
        s1 += __shfl_xor_sync(0xffffffffu, s1, 1);
        if ((tg & 1) == 0) {
            int grp = ((nf & 1) << 1) | (tg >> 1);
            g_g4[f * (B_SZ * 4) + row * 4 + grp] = s0;
            g_g4[f * (B_SZ * 4) + (row + 8) * 4 + grp] = s1;
        }
    }
}

// ---------------------------------------------------------------------------
// Kernel 2: wide scan + scalar precheck. Block (f, p): j-chunks jc=p and
// jc=15-p (uniform). 256 thr = 32 j-lanes x 8 i-groups. Phase 1: scalar
// row-sum bound |S_i - S_j| -> keep-bit in a SCALAR register mask (LDS.32
// broadcast + FADD + FSETP + pred-OR per eval). Phase 2: per-bit 4-group
// bound (LDS.128), then exact fp32 norm+exp+absorb from L2; skip +0 adds.
// ---------------------------------------------------------------------------
__global__ void __launch_bounds__(256) boundexp(const float* __restrict__ X,
                                                float* __restrict__ out) {
    __shared__ float sv[B_SZ];                 // scalar row sums
    __shared__ float sg4[B_SZ * 4];            // 4-group sums
    // (sv+sg4 = 10KB)

    const int f = blockIdx.x, p = blockIdx.y;  // p in [0,8)
    const int tid = threadIdx.x, jl = tid & 31, ig = tid >> 5;  // ig 0..7
    const int stage_rows = (16 - p) * 32;      // covers both chunks

    // folded x-copy: 65536 float4s over 512 blocks
    if (tid < 128) {
        int idx4 = (f * 8 + p) * 128 + tid;
        int b = idx4 >> 7, c4 = idx4 & 127;
        ((float4*)(out + b * OUT_W))[c4] = ((const float4*)(X + b * IN_F))[c4];
    }
    {
        const float4* src = (const float4*)(g_g4 + f * (B_SZ * 4));
        for (int idx = tid; idx < stage_rows; idx += 256) {
            float4 v = src[idx];
            ((float4*)sg4)[idx] = v;
            sv[idx] = (v.x + v.y) + (v.z + v.w);
        }
    }
    __syncthreads();

    const float4* mf4 = (const float4*)(g_m2 + f * (B_SZ * K_DIMS));

#pragma unroll
    for (int cc = 0; cc < 2; ++cc) {
        const int jc = cc ? (15 - p) : p;
        const int imax = (jc + 1) * 32;
        const int j = jc * 32 + jl;
        const float sj = sv[j];
        const float4 hj = ((const float4*)sg4)[j];
        const int nb_max = imax >> 3;          // i = ig + nb*8
        // i < j  <=>  nb < nb_lim (hoisted out of the hot loop)
        const int nb_lim = (j > ig) ? ((j - ig + 7) >> 3) : 0;

        for (int base = 0; base < nb_max; base += 32) {
            const int lim = min(32, nb_max - base);
            uint32_t msk = 0u;                 // scalar: stays in a reg
#pragma unroll 8
            for (int b = 0; b < lim; ++b) {
                int i = ig + (base + b) * 8;
                float d = fabsf(sv[i] - sj);   // LDS.32 broadcast
                if (d < THRESH) msk |= 1u << b;
            }
            // apply i<j once per chunk
            int rel = nb_lim - base;
            uint32_t allowed = (rel <= 0) ? 0u
                             : (rel >= 32) ? 0xffffffffu : ((1u << rel) - 1u);
            msk &= allowed;

            while (msk) {                      // ~11% of pairs land here
                int b = __ffs(msk) - 1;
                msk &= msk - 1;
                int i = ig + (base + b) * 8;
                float4 a = ((const float4*)sg4)[i];
                float bnd = (fabsf(a.x - hj.x) + fabsf(a.y - hj.y)) +
                            (fabsf(a.z - hj.z) + fabsf(a.w - hj.w));
                if (bnd >= THRESH) continue;   // 4-group bound
                const float4* mi = mf4 + i * 4;    // exact (L2)
                const float4* mj = mf4 + j * 4;
                float norm = 0.f;
#pragma unroll
                for (int pp = 0; pp < 4; ++pp) {
                    float4 u = mi[pp], v = mj[pp];
                    norm += (fabsf(u.x - v.x) + fabsf(u.y - v.y)) +
                            (fabsf(u.z - v.z) + fabsf(u.w - v.w));
                }
                // fp32 absorption vs self-term 1.0: ex <= 2^-24 -> +0.0f;
                // skipping a +0.0 add is bitwise identical.
                float ex = __expf(-norm);
                float exa = __fadd_rn(__fadd_rn(1.0f, ex), -1.0f);
                if (exa != 0.0f) {
                    atomicAdd(&out[j * OUT_W + IN_F + f], exa);  // both sides
                    atomicAdd(&out[i * OUT_W + IN_F + f], exa);
                }
            }
        }
    }
}

// ---------------------------------------------------------------------------
extern "C" void kernel_launch(void* const* d_in, const int* in_sizes, int n_in,
                              void* d_out, int out_size) {
    const float* X = (const float*)d_in[0];   // [512, 512]
    const float* T = (const float*)d_in[1];   // [512, 64, 16]
    float* out = (float*)d_out;               // [512, 576]

    // host-side attribute set (not a stream op; capture-safe, deterministic)
    cudaFuncSetAttribute(gemm_tc, cudaFuncAttributeMaxDynamicSharedMemorySize,
                         GEMM_SMEM_BYTES);

    gemm_tc<<<dim3(16, 8), 512, GEMM_SMEM_BYTES>>>(X, T, out);
    boundexp<<<dim3(OUT_F, 8), 256>>>(X, out);
}